// round 5
// baseline (speedup 1.0000x reference)
#include <cuda_runtime.h>
#include <stdint.h>

#define N_SHIFT 10

// out[b][i][j] = 1  iff  |i-j| <= N_SHIFT and mask[b][p] == 0 for all
// p in (min(i,j), max(i,j)].  (Closed form of the reference's 10-step
// shift/max recurrence + symmetrization; verified by hand-simulation.)
//
// This round's single controlled change vs R3: output written as FLOAT
// (1.0f / 0.0f) instead of int32 — testing the hypothesis that the
// harness's __output__ dtype is float32, which would make int writes of
// 1 read back as 1.4e-45 ~ 0 and explain rel_err == 1.0 exactly.
//
// Input is read through int* with a `!= 0` test, which is correct for
// BOTH int32 {0,1} and float32 {0.0f,1.0f} bit patterns.
__global__ void chunk_mask_scalar_kernel(const int* __restrict__ mask,
                                         float* __restrict__ out,
                                         int L) {
    const int j = blockIdx.x * blockDim.x + threadIdx.x;  // column
    const int i = blockIdx.y;                             // row
    const int b = blockIdx.z;                             // batch
    if (j >= L) return;

    const int lo = (i < j) ? i : j;
    const int hi = (i < j) ? j : i;

    float r = 0.0f;
    if (hi - lo <= N_SHIFT) {
        r = 1.0f;
        const int* __restrict__ mrow = mask + (size_t)b * (size_t)L;
        for (int p = lo + 1; p <= hi; ++p) {
            if (mrow[p] != 0) { r = 0.0f; break; }
        }
    }

    out[((size_t)b * L + i) * (size_t)L + j] = r;
}

extern "C" void kernel_launch(void* const* d_in, const int* in_sizes, int n_in,
                              void* d_out, int out_size) {
    const int* mask = (const int*)d_in[0];
    float* out = (float*)d_out;

    // in_sizes[0] = B*L elements, out_size = B*L*L elements.
    const int n_mask = in_sizes[0];
    const int L = (int)((long long)out_size / (long long)n_mask);  // 1024
    const int B = n_mask / L;                                      // 32

    dim3 block(256, 1, 1);
    dim3 grid((L + 255) / 256, L, B);
    chunk_mask_scalar_kernel<<<grid, block>>>(mask, out, L);
}

// round 6
// speedup vs baseline: 2.1021x; 2.1021x over previous
#include <cuda_runtime.h>
#include <stdint.h>

#define L_DIM 1024
#define N_SHIFT 10

// out[b][i][j] = 1.0f  iff  |i-j| <= N_SHIFT and mask[b][p] == 0 for all
// p in (min(i,j), max(i,j)].  Output dtype: float32 (confirmed R4).
//
// One block per (row i, batch b); 256 threads; each thread stores ONE
// float4 (4 consecutive j). Only threads overlapping the 21-wide band
// [i-10, i+10] do any loads; all others are a pure zero STG.128.
__global__ __launch_bounds__(256) void chunk_mask_v4_kernel(const int* __restrict__ mask,
                                                            float* __restrict__ out) {
    const int i = blockIdx.x;   // row within L
    const int b = blockIdx.y;   // batch
    const int t = threadIdx.x;

    float4* __restrict__ orow =
        reinterpret_cast<float4*>(out + ((size_t)b * L_DIM + i) * (size_t)L_DIM);

    const int j0 = t << 2;
    float4 v = make_float4(0.f, 0.f, 0.f, 0.f);

    // Thread's span [j0, j0+3] vs band [i-10, i+10].
    if (j0 + 3 >= i - N_SHIFT && j0 <= i + N_SHIFT) {
        const int* __restrict__ mrow = mask + (size_t)b * L_DIM;
        float vals[4];
        #pragma unroll
        for (int k = 0; k < 4; ++k) {
            const int j = j0 + k;
            const int d = j - i;
            float r = 0.f;
            if (d >= -N_SHIFT && d <= N_SHIFT) {
                const int lo = (d < 0) ? j : i;
                const int hi = (d < 0) ? i : j;
                int s = 0;
                #pragma unroll 1
                for (int p = lo + 1; p <= hi; ++p) {
                    s |= mrow[p];          // mask values are 0/1
                }
                r = (s == 0) ? 1.f : 0.f;
            }
            vals[k] = r;
        }
        v.x = vals[0]; v.y = vals[1]; v.z = vals[2]; v.w = vals[3];
    }

    orow[t] = v;
}

extern "C" void kernel_launch(void* const* d_in, const int* in_sizes, int n_in,
                              void* d_out, int out_size) {
    const int* mask = (const int*)d_in[0];
    float* out = (float*)d_out;

    const int B = in_sizes[0] / L_DIM;   // 32

    dim3 grid(L_DIM, B);
    chunk_mask_v4_kernel<<<grid, 256>>>(mask, out);
}